// round 1
// baseline (speedup 1.0000x reference)
#include <cuda_runtime.h>

// Problem constants (fixed by the dataset: B=4, N=1e6, H=W=128)
#define BATCH 4
#define NEV   1000000
#define HDIM  128
#define WDIM  128
#define HW    (HDIM * WDIM)

// Kernel 1: write avg_flow channels (2,3) and zero the IWE channels (0,1).
// One thread per (b, h*w) pixel.
__global__ void init_out_kernel(const float* __restrict__ flow,
                                const float* __restrict__ event_mask,
                                float* __restrict__ out) {
    int i = blockIdx.x * blockDim.x + threadIdx.x;   // over BATCH*HW
    if (i >= BATCH * HW) return;
    int b = i / HW;
    int p = i - b * HW;

    float m = event_mask[i];                 // [B,1,H,W] flattened == i
    float s = m / (m + 1e-9f);               // exact same arithmetic as ref

    const float* fb = flow + (size_t)b * 2 * HW;
    float* ob = out + (size_t)b * 4 * HW;

    ob[p]            = 0.0f;                 // iwe_pos
    ob[HW + p]       = 0.0f;                 // iwe_neg
    ob[2 * HW + p]   = fb[p]      * s;       // avg_flow ch0
    ob[3 * HW + p]   = fb[HW + p] * s;       // avg_flow ch1
}

// Kernel 2: per-event bilinear scatter. One thread per event.
__global__ void scatter_kernel(const float4* __restrict__ ev,   // [B*N] (ts,y,x,p)
                               const float* __restrict__ flow,  // [B,2,H,W]
                               float* __restrict__ out) {       // [B,4,H,W]
    int i = blockIdx.x * blockDim.x + threadIdx.x;
    if (i >= BATCH * NEV) return;
    int b = i / NEV;

    float4 e = ev[i];
    float ts = e.x, y = e.y, x = e.z, p = e.w;

    // flow_idx = round(y)*W + round(x); y,x are integer-valued -> exact
    int gidx = __float2int_rn(y) * WDIM + __float2int_rn(x);

    const float* fb = flow + (size_t)b * 2 * HW;
    float ef_x = __ldg(fb + gidx);           // flow channel 0 -> x displacement
    float ef_y = __ldg(fb + HW + gidx);      // flow channel 1 -> y displacement

    // warped = (y,x) + (1 - ts) * (ef_y, ef_x)
    float dt = 1.0f - ts;
    float wy = y + dt * ef_y;
    float wx = x + dt * ef_x;

    float tyf = floorf(wy);
    float lxf = floorf(wx);
    float fy = wy - tyf;                     // in [0,1)
    float fx = wx - lxf;

    int ty = (int)tyf;                       // safe: |flow| small, wy in ~[-30, 160]
    int lx = (int)lxf;
    int by = ty + 1;
    int rx = lx + 1;

    float w_t = 1.0f - fy, w_b = fy;         // == max(0, 1-|wy - corner_y|)
    float w_l = 1.0f - fx, w_r = fx;

    bool ok_t = (ty >= 0) & (ty < HDIM);
    bool ok_b = (by >= 0) & (by < HDIM);
    bool ok_l = (lx >= 0) & (lx < WDIM);
    bool ok_r = (rx >= 0) & (rx < WDIM);

    // pol_mask = (p, 1-p), p in {0,1}: each event hits exactly one channel
    int ch = (p > 0.5f) ? 0 : 1;
    float* base = out + (size_t)b * 4 * HW + (size_t)ch * HW;

    float w;
    if (ok_t & ok_l) { w = w_t * w_l; if (w != 0.0f) atomicAdd(base + ty * WDIM + lx, w); }
    if (ok_t & ok_r) { w = w_t * w_r; if (w != 0.0f) atomicAdd(base + ty * WDIM + rx, w); }
    if (ok_b & ok_l) { w = w_b * w_l; if (w != 0.0f) atomicAdd(base + by * WDIM + lx, w); }
    if (ok_b & ok_r) { w = w_b * w_r; if (w != 0.0f) atomicAdd(base + by * WDIM + rx, w); }
}

extern "C" void kernel_launch(void* const* d_in, const int* in_sizes, int n_in,
                              void* d_out, int out_size) {
    const float* flow       = (const float*)d_in[0];   // [B,2,H,W]
    const float* event_list = (const float*)d_in[1];   // [B,N,4]
    // d_in[2] (pol_mask) intentionally unused: pol_mask == (p, 1-p) from event_list
    const float* event_mask = (const float*)d_in[3];   // [B,1,H,W]
    float* out = (float*)d_out;                        // [B,4,H,W]

    {
        int n = BATCH * HW;
        int threads = 256;
        init_out_kernel<<<(n + threads - 1) / threads, threads>>>(flow, event_mask, out);
    }
    {
        int n = BATCH * NEV;
        int threads = 256;
        scatter_kernel<<<(n + threads - 1) / threads, threads>>>(
            (const float4*)event_list, flow, out);
    }
}

// round 2
// speedup vs baseline: 1.8256x; 1.8256x over previous
#include <cuda_runtime.h>

// Problem constants (fixed by the dataset: B=4, N=1e6, H=W=128)
#define BATCH 4
#define NEV   1000000
#define HDIM  128
#define WDIM  128
#define HW    (HDIM * WDIM)

// Interleaved flow scratch: g_flow_i[b*HW + p] = (flow_x, flow_y) at pixel p.
// __device__ global (no dynamic allocation — 512 KB).
__device__ float2 g_flow_i[BATCH * HW];

// Kernel 1: write avg_flow channels (2,3), zero the IWE channels (0,1),
// and build the interleaved flow scratch. One thread per (b, pixel).
__global__ void init_out_kernel(const float* __restrict__ flow,
                                const float* __restrict__ event_mask,
                                float* __restrict__ out) {
    int i = blockIdx.x * blockDim.x + threadIdx.x;   // over BATCH*HW
    if (i >= BATCH * HW) return;
    int b = i / HW;
    int p = i - b * HW;

    float m = event_mask[i];                 // [B,1,H,W] flattened == i
    float s = m / (m + 1e-9f);               // exact same arithmetic as ref

    const float* fb = flow + (size_t)b * 2 * HW;
    float fx = fb[p];
    float fy = fb[HW + p];
    g_flow_i[i] = make_float2(fx, fy);

    float* ob = out + (size_t)b * 4 * HW;
    ob[p]          = 0.0f;                   // iwe_pos
    ob[HW + p]     = 0.0f;                   // iwe_neg
    ob[2 * HW + p] = fx * s;                 // avg_flow ch0
    ob[3 * HW + p] = fy * s;                 // avg_flow ch1
}

// Vector global reduction: one instruction adds 4 floats at a 16B-aligned addr.
__device__ __forceinline__ void red_v4(float* p, float a, float b, float c, float d) {
    asm volatile("red.global.add.v4.f32 [%0], {%1, %2, %3, %4};"
                 :: "l"(p), "f"(a), "f"(b), "f"(c), "f"(d) : "memory");
}

// Emit the two x-corners (columns lx, lx+1) of one row with weights wl, wr.
// rowp points at column 0 of a valid row (16B aligned).
__device__ __forceinline__ void emit_row(float* rowp, int lx, float wl, float wr) {
    int rx = lx + 1;
    bool okl = (lx >= 0) & (lx < WDIM);
    bool okr = (rx >= 0) & (rx < WDIM);
    wl = okl ? wl : 0.0f;
    wr = okr ? wr : 0.0f;

    if (wl == 0.0f) {                         // left corner dead (OOB or zero wt)
        if (wr != 0.0f) atomicAdd(rowp + rx, wr);
        return;
    }
    if (wr == 0.0f) {
        atomicAdd(rowp + lx, wl);
        return;
    }
    // Both corners live: 0 <= lx <= 126.
    int s = lx & 3;
    if (s < 3) {
        // Both in the same 16B group -> one vector reduction (zero-padded).
        float v0 = (s == 0) ? wl : 0.0f;
        float v1 = (s == 0) ? wr : ((s == 1) ? wl : 0.0f);
        float v2 = (s == 1) ? wr : ((s == 2) ? wl : 0.0f);
        float v3 = (s == 2) ? wr : 0.0f;
        red_v4(rowp + (lx & ~3), v0, v1, v2, v3);
    } else {
        // Split across groups: two scalar reductions.
        atomicAdd(rowp + lx, wl);
        atomicAdd(rowp + rx, wr);
    }
}

// Kernel 2: per-event bilinear scatter. One thread per event.
__global__ void scatter_kernel(const float4* __restrict__ ev,   // [B*N] (ts,y,x,p)
                               float* __restrict__ out) {       // [B,4,H,W]
    int i = blockIdx.x * blockDim.x + threadIdx.x;
    if (i >= BATCH * NEV) return;
    int b = i / NEV;

    float4 e = ev[i];
    float ts = e.x, y = e.y, x = e.z, p = e.w;

    // flow_idx = round(y)*W + round(x); y,x are integer-valued -> exact
    int gidx = __float2int_rn(y) * WDIM + __float2int_rn(x);
    float2 f = __ldg(&g_flow_i[b * HW + gidx]);   // (ef_x, ef_y), one LDG.64

    // warped = (y,x) + (1 - ts) * (ef_y, ef_x)
    float dt = 1.0f - ts;
    float wy = fmaf(dt, f.y, y);
    float wx = fmaf(dt, f.x, x);

    float tyf = floorf(wy);
    float lxf = floorf(wx);
    float fy = wy - tyf;                     // in [0,1)
    float fx = wx - lxf;

    int ty = (int)tyf;
    int lx = (int)lxf;
    int by = ty + 1;

    // pol_mask = (p, 1-p), p in {0,1}: each event hits exactly one channel
    int ch = (p > 0.5f) ? 0 : 1;
    float* base = out + (size_t)b * 4 * HW + (size_t)ch * HW;

    if (ty >= 0 && ty < HDIM)
        emit_row(base + ty * WDIM, lx, (1.0f - fy) * (1.0f - fx), (1.0f - fy) * fx);
    if (by >= 0 && by < HDIM)
        emit_row(base + by * WDIM, lx, fy * (1.0f - fx), fy * fx);
}

extern "C" void kernel_launch(void* const* d_in, const int* in_sizes, int n_in,
                              void* d_out, int out_size) {
    const float* flow       = (const float*)d_in[0];   // [B,2,H,W]
    const float* event_list = (const float*)d_in[1];   // [B,N,4]
    // d_in[2] (pol_mask) intentionally unused: pol_mask == (p, 1-p) from event_list
    const float* event_mask = (const float*)d_in[3];   // [B,1,H,W]
    float* out = (float*)d_out;                        // [B,4,H,W]

    {
        int n = BATCH * HW;
        int threads = 256;
        init_out_kernel<<<(n + threads - 1) / threads, threads>>>(flow, event_mask, out);
    }
    {
        int n = BATCH * NEV;
        int threads = 256;
        scatter_kernel<<<(n + threads - 1) / threads, threads>>>(
            (const float4*)event_list, out);
    }
}

// round 5
// speedup vs baseline: 2.2219x; 1.2170x over previous
#include <cuda_runtime.h>

// Problem constants (fixed by the dataset: B=4, N=1e6, H=W=128)
#define BATCH 4
#define NEV   1000000
#define HDIM  128
#define WDIM  128
#define HW    (HDIM * WDIM)

#define CTAS_PER_BATCH 37
#define GRID_SCATTER   (BATCH * CTAS_PER_BATCH)          // 148 = one CTA per SM
#define EV_PER_CTA     ((NEV + CTAS_PER_BATCH - 1) / CTAS_PER_BATCH)  // 27028
#define SMEM_BYTES     (HW * sizeof(float2))             // 128 KB

// Kernel 1: write avg_flow channels (2,3) and zero the IWE channels (0,1).
__global__ void init_out_kernel(const float* __restrict__ flow,
                                const float* __restrict__ event_mask,
                                float* __restrict__ out) {
    int i = blockIdx.x * blockDim.x + threadIdx.x;   // over BATCH*HW
    if (i >= BATCH * HW) return;
    int b = i / HW;
    int p = i - b * HW;

    float m = event_mask[i];
    float s = m / (m + 1e-9f);               // exact same arithmetic as ref

    const float* fb = flow + (size_t)b * 2 * HW;
    float* ob = out + (size_t)b * 4 * HW;

    ob[p]          = 0.0f;                   // iwe_pos
    ob[HW + p]     = 0.0f;                   // iwe_neg
    ob[2 * HW + p] = fb[p]      * s;         // avg_flow ch0
    ob[3 * HW + p] = fb[HW + p] * s;         // avg_flow ch1
}

// Vector global reduction: one instruction adds 4 floats at a 16B-aligned addr.
__device__ __forceinline__ void red_v4(float* p, float a, float b, float c, float d) {
    asm volatile("red.global.add.v4.f32 [%0], {%1, %2, %3, %4};"
                 :: "l"(p), "f"(a), "f"(b), "f"(c), "f"(d) : "memory");
}

// Emit the two x-corners (columns lx, lx+1) of one valid row.
__device__ __forceinline__ void emit_row(float* rowp, int lx, float wl, float wr) {
    int rx = lx + 1;
    bool okl = (lx >= 0) & (lx < WDIM);
    bool okr = (rx >= 0) & (rx < WDIM);
    wl = okl ? wl : 0.0f;
    wr = okr ? wr : 0.0f;

    if (wl == 0.0f) {
        if (wr != 0.0f) atomicAdd(rowp + rx, wr);
        return;
    }
    if (wr == 0.0f) {
        atomicAdd(rowp + lx, wl);
        return;
    }
    int s = lx & 3;
    if (s < 3) {
        float v0 = (s == 0) ? wl : 0.0f;
        float v1 = (s == 0) ? wr : ((s == 1) ? wl : 0.0f);
        float v2 = (s == 1) ? wr : ((s == 2) ? wl : 0.0f);
        float v3 = (s == 2) ? wr : 0.0f;
        red_v4(rowp + (lx & ~3), v0, v1, v2, v3);
    } else {
        atomicAdd(rowp + lx, wl);
        atomicAdd(rowp + rx, wr);
    }
}

// Kernel 2: batch-partitioned scatter with flow staged in shared memory.
// 148 CTAs (one wave), 37 per batch, 1024 threads each.
__global__ __launch_bounds__(1024, 1)
void scatter_kernel(const float4* __restrict__ ev,   // [B*N] (ts,y,x,p)
                    const float* __restrict__ flow,  // [B,2,H,W]
                    float* __restrict__ out) {       // [B,4,H,W]
    extern __shared__ float2 sflow[];                // [HW] = 128 KB

    int b = blockIdx.x / CTAS_PER_BATCH;
    int c = blockIdx.x - b * CTAS_PER_BATCH;

    // Stage this batch's flow, interleaved (fx, fy), via coalesced float4 loads.
    const float4* fx4 = (const float4*)(flow + (size_t)b * 2 * HW);
    const float4* fy4 = (const float4*)(flow + (size_t)b * 2 * HW + HW);
    for (int i = threadIdx.x; i < HW / 4; i += blockDim.x) {
        float4 a = fx4[i];
        float4 d = fy4[i];
        sflow[4 * i + 0] = make_float2(a.x, d.x);
        sflow[4 * i + 1] = make_float2(a.y, d.y);
        sflow[4 * i + 2] = make_float2(a.z, d.z);
        sflow[4 * i + 3] = make_float2(a.w, d.w);
    }
    __syncthreads();

    const float4* evb = ev + (size_t)b * NEV;
    float* ob = out + (size_t)b * 4 * HW;

    int e0 = c * EV_PER_CTA;
    int e1 = e0 + EV_PER_CTA; if (e1 > NEV) e1 = NEV;

    #pragma unroll 4
    for (int i = e0 + threadIdx.x; i < e1; i += blockDim.x) {
        float4 e = evb[i];
        float ts = e.x, y = e.y, x = e.z, p = e.w;

        // flow_idx = round(y)*W + round(x); y,x are integer-valued -> exact
        int gidx = __float2int_rn(y) * WDIM + __float2int_rn(x);
        float2 f = sflow[gidx];                  // (ef_x, ef_y), one LDS.64

        float dt = 1.0f - ts;
        float wy = fmaf(dt, f.y, y);
        float wx = fmaf(dt, f.x, x);

        float tyf = floorf(wy);
        float lxf = floorf(wx);
        float fy = wy - tyf;
        float fx = wx - lxf;

        int ty = (int)tyf;
        int lx = (int)lxf;
        int by = ty + 1;

        // pol_mask = (p, 1-p), p in {0,1}: each event hits exactly one channel
        float* base = ob + ((p > 0.5f) ? 0 : HW);

        if (ty >= 0 && ty < HDIM)
            emit_row(base + ty * WDIM, lx, (1.0f - fy) * (1.0f - fx), (1.0f - fy) * fx);
        if (by >= 0 && by < HDIM)
            emit_row(base + by * WDIM, lx, fy * (1.0f - fx), fy * fx);
    }
}

extern "C" void kernel_launch(void* const* d_in, const int* in_sizes, int n_in,
                              void* d_out, int out_size) {
    const float* flow       = (const float*)d_in[0];   // [B,2,H,W]
    const float* event_list = (const float*)d_in[1];   // [B,N,4]
    // d_in[2] (pol_mask) intentionally unused: pol_mask == (p, 1-p) from event_list
    const float* event_mask = (const float*)d_in[3];   // [B,1,H,W]
    float* out = (float*)d_out;                        // [B,4,H,W]

    // Idempotent, non-syncing host-side config (no static guard: kernel_launch
    // must be stateless and deterministic).
    cudaFuncSetAttribute(scatter_kernel,
                         cudaFuncAttributeMaxDynamicSharedMemorySize, SMEM_BYTES);

    {
        int n = BATCH * HW;
        int threads = 256;
        init_out_kernel<<<(n + threads - 1) / threads, threads>>>(flow, event_mask, out);
    }
    scatter_kernel<<<GRID_SCATTER, 1024, SMEM_BYTES>>>(
        (const float4*)event_list, flow, out);
}